// round 1
// baseline (speedup 1.0000x reference)
#include <cuda_runtime.h>
#include <math_constants.h>
#include <cstdint>

#define DIM     128
#define BM      64
#define BN      64
#define KSEL    10
#define NSPLIT  10
#define MAXB    2048
#define MAXN    100000

// ---------------- device scratch (no allocations allowed) ----------------
__device__ float g_wmax;
__device__ float g_c[MAXN];                       // x2[n] + wp2[n]
__device__ float g_keys[MAXB * NSPLIT * KSEL];
__device__ int   g_idxs[MAXB * NSPLIT * KSEL];

// ---------------- tiny init ----------------
__global__ void init_kernel() { g_wmax = 0.0f; }

// ---------------- max(relu(w)) ----------------
__global__ void wmax_kernel(const float* __restrict__ w, int n) {
    float m = 0.0f;
    for (int i = blockIdx.x * blockDim.x + threadIdx.x; i < n;
         i += gridDim.x * blockDim.x)
        m = fmaxf(m, w[i]);                     // init 0 => relu folded in
    #pragma unroll
    for (int o = 16; o; o >>= 1) m = fmaxf(m, __shfl_xor_sync(0xffffffffu, m, o));
    __shared__ float sm[32];
    int lane = threadIdx.x & 31, wid = threadIdx.x >> 5;
    if (lane == 0) sm[wid] = m;
    __syncthreads();
    if (wid == 0) {
        m = (lane < (int)(blockDim.x >> 5)) ? sm[lane] : 0.0f;
        #pragma unroll
        for (int o = 16; o; o >>= 1) m = fmaxf(m, __shfl_xor_sync(0xffffffffu, m, o));
        // values are >= 0 so int compare == float compare
        if (lane == 0) atomicMax((int*)&g_wmax, __float_as_int(m));
    }
}

// ---------------- c[n] = ||X_n||^2 + (wmax - w[n]) ----------------
__global__ void c_kernel(const float* __restrict__ X, const float* __restrict__ w, int n) {
    int i = blockIdx.x * blockDim.x + threadIdx.x;
    if (i >= n) return;
    const float4* xr = (const float4*)(X + (size_t)i * DIM);
    float s = 0.0f;
    #pragma unroll
    for (int j = 0; j < DIM / 4; j++) {
        float4 v = xr[j];
        s = fmaf(v.x, v.x, s); s = fmaf(v.y, v.y, s);
        s = fmaf(v.z, v.z, s); s = fmaf(v.w, v.w, s);
    }
    g_c[i] = s + (g_wmax - w[i]);
}

// ---------------- main: tiled dot + per-query top-10 over a candidate split ----
__global__ void __launch_bounds__(256)
topk_kernel(const float* __restrict__ xt, const float* __restrict__ Xg, int B, int N) {
    extern __shared__ unsigned char smem_raw[];
    float (*As)[BM]   = (float (*)[BM])(smem_raw);                        // 32 KB
    float (*Bs)[BN]   = (float (*)[BN])(smem_raw + DIM * BM * 4);         // 32 KB
    float (*sKey)[KSEL] = (float (*)[KSEL])(smem_raw + DIM * (BM + BN) * 4);
    int   (*sIdx)[KSEL] = (int   (*)[KSEL])((unsigned char*)sKey + BM * KSEL * 4);
    float *sThr  = (float*)((unsigned char*)sIdx + BM * KSEL * 4);
    int   *sLock = (int*)  ((unsigned char*)sThr + BM * 4);

    const int tid = threadIdx.x;
    const int tx = tid & 15, ty = tid >> 4;
    const int qbase = blockIdx.x * BM;
    const int split = blockIdx.y;
    const int per = (N + NSPLIT - 1) / NSPLIT;
    const int sBeg = split * per;
    const int sEnd = min(N, sBeg + per);

    for (int i = tid; i < BM * KSEL; i += 256) {
        ((float*)sKey)[i] = CUDART_INF_F;
        ((int*)sIdx)[i]   = 0x7fffffff;
    }
    for (int i = tid; i < BM; i += 256) { sThr[i] = CUDART_INF_F; sLock[i] = 0; }

    // load queries transposed: As[d][m]
    {
        int m = tid & 63, g = tid >> 6;           // g in 0..3
        #pragma unroll
        for (int i = 0; i < 8; i++) {
            int c4 = g + i * 4;                    // 0..31
            float4 v = *(const float4*)(xt + (size_t)(qbase + m) * DIM + c4 * 4);
            As[c4 * 4 + 0][m] = v.x; As[c4 * 4 + 1][m] = v.y;
            As[c4 * 4 + 2][m] = v.z; As[c4 * 4 + 3][m] = v.w;
        }
    }
    __syncthreads();

    const int nChunks = (sEnd - sBeg + BN - 1) / BN;
    for (int ch = 0; ch < nChunks; ch++) {
        const int nbase = sBeg + ch * BN;
        // load candidate tile transposed: Bs[d][n]
        {
            int nl = tid & 63, g = tid >> 6;
            int row = nbase + nl;
            const float* src = Xg + (size_t)row * DIM;
            #pragma unroll
            for (int i = 0; i < 8; i++) {
                int c4 = g + i * 4;
                float4 v = make_float4(0.f, 0.f, 0.f, 0.f);
                if (row < sEnd) v = *(const float4*)(src + c4 * 4);
                Bs[c4 * 4 + 0][nl] = v.x; Bs[c4 * 4 + 1][nl] = v.y;
                Bs[c4 * 4 + 2][nl] = v.z; Bs[c4 * 4 + 3][nl] = v.w;
            }
        }
        __syncthreads();

        float acc[4][4];
        #pragma unroll
        for (int i = 0; i < 4; i++)
            #pragma unroll
            for (int j = 0; j < 4; j++) acc[i][j] = 0.0f;

        #pragma unroll 8
        for (int k = 0; k < DIM; k++) {
            float4 av = *(const float4*)&As[k][ty * 4];
            float4 bv = *(const float4*)&Bs[k][tx * 4];
            float a_[4] = {av.x, av.y, av.z, av.w};
            float b_[4] = {bv.x, bv.y, bv.z, bv.w};
            #pragma unroll
            for (int i = 0; i < 4; i++)
                #pragma unroll
                for (int j = 0; j < 4; j++)
                    acc[i][j] = fmaf(a_[i], b_[j], acc[i][j]);
        }
        __syncthreads();

        // selection: key = c[n] - 2 * dot  (ranking-equivalent to d2)
        #pragma unroll
        for (int j = 0; j < 4; j++) {
            const int n = nbase + tx * 4 + j;
            if (n >= sEnd) continue;
            const float cn = __ldg(&g_c[n]);
            #pragma unroll
            for (int i = 0; i < 4; i++) {
                const int q = ty * 4 + i;
                const float key = fmaf(-2.0f, acc[i][j], cn);
                if (key < sThr[q]) {
                    bool done = false;
                    while (!done) {
                        if (atomicCAS(&sLock[q], 0, 1) == 0) {
                            __threadfence_block();
                            if (key < sThr[q]) {
                                int p = KSEL - 1;
                                while (p > 0 && (sKey[q][p - 1] > key ||
                                       (sKey[q][p - 1] == key && sIdx[q][p - 1] > n))) {
                                    sKey[q][p] = sKey[q][p - 1];
                                    sIdx[q][p] = sIdx[q][p - 1];
                                    p--;
                                }
                                sKey[q][p] = key;
                                sIdx[q][p] = n;
                                sThr[q] = sKey[q][KSEL - 1];
                            }
                            __threadfence_block();
                            atomicExch(&sLock[q], 0);
                            done = true;
                        }
                    }
                }
            }
        }
    }
    __syncthreads();

    for (int i = tid; i < BM * KSEL; i += 256) {
        int q = i / KSEL, j = i % KSEL;
        size_t o = ((size_t)(qbase + q) * NSPLIT + split) * KSEL + j;
        g_keys[o] = sKey[q][j];
        g_idxs[o] = sIdx[q][j];
    }
}

// ---------------- merge partial top-10 lists + rescore + argmax ----------------
__global__ void merge_kernel(const float* __restrict__ xt, const float* __restrict__ w,
                             float* __restrict__ out, int B, int out_size) {
    int b = blockIdx.x * blockDim.x + threadIdx.x;
    if (b >= B) return;
    float kk[NSPLIT * KSEL];
    int   ii[NSPLIT * KSEL];
    for (int i = 0; i < NSPLIT * KSEL; i++) {
        kk[i] = g_keys[(size_t)b * NSPLIT * KSEL + i];
        ii[i] = g_idxs[(size_t)b * NSPLIT * KSEL + i];
    }
    float q2 = 0.0f;
    const float4* xr = (const float4*)(xt + (size_t)b * DIM);
    #pragma unroll
    for (int j = 0; j < DIM / 4; j++) {
        float4 v = xr[j];
        q2 = fmaf(v.x, v.x, q2); q2 = fmaf(v.y, v.y, q2);
        q2 = fmaf(v.z, v.z, q2); q2 = fmaf(v.w, v.w, q2);
    }
    const float wmax = g_wmax;
    float bestF = -CUDART_INF_F;
    int   bestI = 0;
    for (int s = 0; s < KSEL; s++) {
        int pm = -1; float mk = CUDART_INF_F; int mi = 0x7fffffff;
        for (int i = 0; i < NSPLIT * KSEL; i++) {
            if (kk[i] < mk || (kk[i] == mk && ii[i] < mi)) { mk = kk[i]; mi = ii[i]; pm = i; }
        }
        if (pm < 0 || !isfinite(mk)) break;
        kk[pm] = CUDART_INF_F;
        const float wi  = w[mi];
        const float wp2 = wmax - wi;
        const float dd  = q2 + mk - wp2;        // = ||q - x||^2 (up to rounding)
        const float f   = wi - sqrtf(fmaxf(dd, 0.0f));
        if (f > bestF) { bestF = f; bestI = mi; }   // strict > keeps first max
    }
    out[b] = bestF;
    if (out_size >= 2 * B) out[B + b] = (float)bestI;
}

// ---------------- entry ----------------
extern "C" void kernel_launch(void* const* d_in, const int* in_sizes, int n_in,
                              void* d_out, int out_size) {
    const float* xt = (const float*)d_in[0];
    const float* X  = (const float*)d_in[1];
    const float* w  = (const float*)d_in[2];
    const int B = in_sizes[0] / DIM;
    const int N = in_sizes[1] / DIM;

    static bool attr_set = false;
    const int smem_bytes = DIM * (BM + BN) * 4 + BM * KSEL * 8 + BM * 8;
    if (!attr_set) {
        cudaFuncSetAttribute(topk_kernel, cudaFuncAttributeMaxDynamicSharedMemorySize,
                             smem_bytes);
        attr_set = true;
    }

    init_kernel<<<1, 1>>>();
    wmax_kernel<<<160, 256>>>(w, N);
    c_kernel<<<(N + 255) / 256, 256>>>(X, w, N);
    dim3 grid(B / BM, NSPLIT);
    topk_kernel<<<grid, 256, smem_bytes>>>(xt, X, B, N);
    merge_kernel<<<(B + 255) / 256, 256>>>(xt, w, (float*)d_out, B, out_size);
}